// round 1
// baseline (speedup 1.0000x reference)
#include <cuda_runtime.h>
#include <math.h>
#include <float.h>

#define BQ    8192
#define NB    2
#define NQ    (NB*BQ)
#define KNN   16
#define BALL2 0.2f
#define TILE  1024

// ---------------- scratch (no allocations allowed) ----------------
__device__ float4 g_db[NQ];          // ref points as (x,y,z,-0.5*||p||^2)
__device__ float  g_dist[NQ*KNN];    // top-16 squared dists (ascending)
__device__ int    g_idx [NQ*KNN];    // top-16 neighbor indices
__device__ double g_partial[128];    // per-block partial sums

// ---------------- prep: pack db points ----------------
__global__ void prep_kernel(const float* __restrict__ ref) {
    int i = blockIdx.x * blockDim.x + threadIdx.x;
    if (i < NQ) {
        float x = ref[3*i+0], y = ref[3*i+1], z = ref[3*i+2];
        float n = x*x + y*y + z*z;
        g_db[i] = make_float4(x, y, z, -0.5f*n);
    }
}

// ---------------- brute-force KNN ----------------
// 4 lanes per query; each lane scans a strided quarter of the 8192
// candidates keeping a sorted local top-16 in registers, then the 4 lanes
// merge via shuffles. d2 = qn - 2*t where t = q.b - 0.5*||b||^2, so the
// hot loop is 1 LDS.128 + 3 FMA + 1 compare.
__global__ void __launch_bounds__(128) knn_kernel(const float* __restrict__ ref) {
    __shared__ float4 sdb[TILE];
    const int tid = threadIdx.x;
    const int lg  = tid & 3;                      // lane within query-group
    const int b   = blockIdx.x >> 8;              // 256 blocks per batch
    const int n   = ((blockIdx.x & 255) << 5) + (tid >> 2);
    const int q   = b * BQ + n;

    const float qx = ref[3*q+0], qy = ref[3*q+1], qz = ref[3*q+2];
    const float qn = qx*qx + qy*qy + qz*qz;

    float dv[KNN];
    int   iv[KNN];
#pragma unroll
    for (int j = 0; j < KNN; j++) { dv[j] = FLT_MAX; iv[j] = 0x7fffffff; }
    float tcut = -FLT_MAX;

    const float4* dbp = g_db + b * BQ;

    for (int t0 = 0; t0 < BQ; t0 += TILE) {
        __syncthreads();
#pragma unroll
        for (int j = tid; j < TILE; j += 128) sdb[j] = dbp[t0 + j];
        __syncthreads();

#pragma unroll 4
        for (int i = 0; i < TILE/4; i++) {
            const int c = 4*i + lg;
            const float4 p = sdb[c];
            const float tt = fmaf(qx, p.x, fmaf(qy, p.y, fmaf(qz, p.z, p.w)));
            if (tt > tcut) {                       // i.e. d2 < current kth
                const float d2 = fmaf(-2.0f, tt, qn);
                if (d2 < dv[KNN-1]) {
                    dv[KNN-1] = d2; iv[KNN-1] = t0 + c;
#pragma unroll
                    for (int j = KNN-1; j > 0; --j) {
                        if (dv[j] < dv[j-1]) {
                            float td = dv[j]; dv[j] = dv[j-1]; dv[j-1] = td;
                            int   ti = iv[j]; iv[j] = iv[j-1]; iv[j-1] = ti;
                        }
                    }
                    tcut = 0.5f * (qn - dv[KNN-1]);
                }
            }
        }
    }

    // merge the 4 sorted lists: 16 rounds of 4-lane min-select
    for (int r = 0; r < KNN; r++) {
        float bd = dv[0]; int bi = iv[0];
#pragma unroll
        for (int off = 1; off < 4; off <<= 1) {
            float od = __shfl_xor_sync(0xffffffffu, bd, off, 4);
            int   oi = __shfl_xor_sync(0xffffffffu, bi, off, 4);
            if (od < bd || (od == bd && oi < bi)) { bd = od; bi = oi; }
        }
        if (dv[0] == bd && iv[0] == bi) {          // owning lane pops
#pragma unroll
            for (int j = 0; j < KNN-1; j++) { dv[j] = dv[j+1]; iv[j] = iv[j+1]; }
            dv[KNN-1] = FLT_MAX; iv[KNN-1] = 0x7fffffff;
        }
        if (lg == 0) { g_dist[q*KNN + r] = bd; g_idx[q*KNN + r] = bi; }
    }
}

// ---------------- 3x3 symmetric eigen -> condition ratio ----------------
__device__ __forceinline__ double cond_of_gram(
    double g00, double g01, double g02, double g11, double g12, double g22) {
    const double q  = (g00 + g11 + g22) * (1.0/3.0);
    const double p1 = g01*g01 + g02*g02 + g12*g12;
    const double b00 = g00 - q, b11 = g11 - q, b22 = g22 - q;
    const double p2 = b00*b00 + b11*b11 + b22*b22 + 2.0*p1;
    double l0, l2;
    if (p2 <= 0.0) {
        l0 = q; l2 = q;
    } else {
        const double p   = sqrt(p2 * (1.0/6.0));
        const double inv = 1.0 / p;
        const double c00 = b00*inv, c01 = g01*inv, c02 = g02*inv;
        const double c11 = b11*inv, c12 = g12*inv, c22 = b22*inv;
        double detB = c00*(c11*c22 - c12*c12)
                    - c01*(c01*c22 - c12*c02)
                    + c02*(c01*c12 - c11*c02);
        double r = 0.5 * detB;
        r = fmin(1.0, fmax(-1.0, r));
        const double phi = acos(r) * (1.0/3.0);
        l0 = q + 2.0*p*cos(phi);
        l2 = q + 2.0*p*cos(phi + 2.0943951023931953);  // +2*pi/3 -> min eig
    }
    const double s0 = sqrt(fmax(l0, 0.0));
    const double s2 = sqrt(fmax(l2, 0.0));
    return s0 / (s2 + s0);
}

// ---------------- per-query condition numbers + squared diff ----------------
__global__ void __launch_bounds__(128) cond_kernel(
    const float* __restrict__ ref, const float* __restrict__ pts) {
    __shared__ double ssum[128];
    const int tid = threadIdx.x;
    const int q   = blockIdx.x * 128 + tid;
    const int b   = q >> 13;
    const float* rp = ref + (size_t)b * BQ * 3;
    const float* pp = pts + (size_t)b * BQ * 3;

    int   idxs[KNN];
    float msk [KNN];
    float nball = 0.0f;
#pragma unroll
    for (int k = 0; k < KNN; k++) {
        const float d = g_dist[q*KNN + k];
        idxs[k] = g_idx[q*KNN + k];
        const float m = (d < BALL2) ? 1.0f : 0.0f;
        msk[k] = m; nball += m;
    }
    const float invn = 1.0f / nball;

    float px[KNN], py[KNN], pz[KNN];

    // ---- ref branch: masked gather ----
    float cx = 0.f, cy = 0.f, cz = 0.f;
#pragma unroll
    for (int k = 0; k < KNN; k++) {
        const int id = idxs[k];
        float x = rp[3*id+0] * msk[k];
        float y = rp[3*id+1] * msk[k];
        float z = rp[3*id+2] * msk[k];
        px[k] = x; py[k] = y; pz[k] = z;
        cx += x; cy += y; cz += z;
    }
    cx *= invn; cy *= invn; cz *= invn;
    double g00=0, g01=0, g02=0, g11=0, g12=0, g22=0;
#pragma unroll
    for (int k = 0; k < KNN; k++) {
        const double dx = (double)(px[k] - cx);
        const double dy = (double)(py[k] - cy);
        const double dz = (double)(pz[k] - cz);
        g00 += dx*dx; g01 += dx*dy; g02 += dx*dz;
        g11 += dy*dy; g12 += dy*dz; g22 += dz*dz;
    }
    const double cond_ref = cond_of_gram(g00, g01, g02, g11, g12, g22);

    // ---- points branch: UNmasked gather (reference discards the mask here) ----
    cx = 0.f; cy = 0.f; cz = 0.f;
#pragma unroll
    for (int k = 0; k < KNN; k++) {
        const int id = idxs[k];
        float x = pp[3*id+0];
        float y = pp[3*id+1];
        float z = pp[3*id+2];
        px[k] = x; py[k] = y; pz[k] = z;
        cx += x; cy += y; cz += z;
    }
    cx *= invn; cy *= invn; cz *= invn;
    g00=0; g01=0; g02=0; g11=0; g12=0; g22=0;
#pragma unroll
    for (int k = 0; k < KNN; k++) {
        const double dx = (double)(px[k] - cx);
        const double dy = (double)(py[k] - cy);
        const double dz = (double)(pz[k] - cz);
        g00 += dx*dx; g01 += dx*dy; g02 += dx*dz;
        g11 += dy*dy; g12 += dy*dz; g22 += dz*dz;
    }
    const double cond_p = cond_of_gram(g00, g01, g02, g11, g12, g22);

    const double diff = cond_p - cond_ref;
    ssum[tid] = diff * diff;
    __syncthreads();
    for (int s = 64; s > 0; s >>= 1) {
        if (tid < s) ssum[tid] += ssum[tid + s];
        __syncthreads();
    }
    if (tid == 0) g_partial[blockIdx.x] = ssum[0];
}

// ---------------- deterministic final reduction ----------------
__global__ void reduce_kernel(float* __restrict__ out) {
    __shared__ double s[128];
    const int tid = threadIdx.x;
    s[tid] = g_partial[tid];
    __syncthreads();
    for (int st = 64; st > 0; st >>= 1) {
        if (tid < st) s[tid] += s[tid + st];
        __syncthreads();
    }
    if (tid == 0) out[0] = (float)(s[0] / (double)NQ);
}

// ---------------- launch ----------------
extern "C" void kernel_launch(void* const* d_in, const int* in_sizes, int n_in,
                              void* d_out, int out_size) {
    const float* ref = (const float*)d_in[0];
    const float* pts = (const float*)d_in[1];
    prep_kernel<<<(NQ + 255)/256, 256>>>(ref);
    knn_kernel<<<512, 128>>>(ref);
    cond_kernel<<<NQ/128, 128>>>(ref, pts);
    reduce_kernel<<<1, 128>>>((float*)d_out);
}

// round 2
// speedup vs baseline: 3.6780x; 3.6780x over previous
#include <cuda_runtime.h>
#include <math.h>
#include <float.h>

#define BQ    8192
#define NB    2
#define NQ    (NB*BQ)
#define KNN   16
#define BALL2 0.2f
#define GR    8
#define GC    (GR*GR*GR)
#define HCELL 0.125f

// ---------------- scratch (no allocations allowed) ----------------
__device__ float4 g_db[NQ];          // packed (x,y,z,-0.5*||p||^2), input order
__device__ int    g_pcell[NQ];       // cell id per point
__device__ int    g_cnt[NB][GC];     // per-cell counts
__device__ int    g_start[NB][GC+1]; // exclusive prefix (per batch)
__device__ int    g_cur[NB][GC];     // scatter cursors
__device__ float4 g_spts[NQ];        // cell-sorted points
__device__ int    g_sidx[NQ];        // original local index of sorted point
__device__ float  g_dist[NQ*KNN];    // top-16 squared dists (ascending)
__device__ int    g_idx [NQ*KNN];    // top-16 neighbor local indices
__device__ double g_partial[128];    // per-block partial sums

__device__ __forceinline__ int cid1(float v) {
    int c = (int)(v * (float)GR);
    return min(GR - 1, max(c, 0));
}

// ---------------- grid build ----------------
__global__ void zero_kernel() {
    int i = blockIdx.x * blockDim.x + threadIdx.x;
    if (i < NB * GC) ((int*)g_cnt)[i] = 0;
}

__global__ void count_kernel(const float* __restrict__ ref) {
    int i = blockIdx.x * blockDim.x + threadIdx.x;
    if (i >= NQ) return;
    float x = ref[3*i+0], y = ref[3*i+1], z = ref[3*i+2];
    float n = x*x + y*y + z*z;
    g_db[i] = make_float4(x, y, z, -0.5f*n);
    int cell = (cid1(z) * GR + cid1(y)) * GR + cid1(x);
    g_pcell[i] = cell;
    atomicAdd(&g_cnt[i >> 13][cell], 1);
}

// one block per batch, 512 threads, Hillis-Steele inclusive scan
__global__ void scan_kernel() {
    __shared__ int s[GC];
    const int b = blockIdx.x, t = threadIdx.x;
    const int cnt = g_cnt[b][t];
    s[t] = cnt;
    __syncthreads();
    for (int off = 1; off < GC; off <<= 1) {
        int v = (t >= off) ? s[t - off] : 0;
        __syncthreads();
        s[t] += v;
        __syncthreads();
    }
    g_start[b][t + 1] = s[t];
    g_cur[b][t] = s[t] - cnt;
    if (t == 0) g_start[b][0] = 0;
}

__global__ void scatter_kernel() {
    int i = blockIdx.x * blockDim.x + threadIdx.x;
    if (i >= NQ) return;
    const int b = i >> 13;
    const int pos = atomicAdd(&g_cur[b][g_pcell[i]], 1);
    g_spts[b * BQ + pos] = g_db[i];
    g_sidx[b * BQ + pos] = i & (BQ - 1);
}

// ---------------- grid KNN: expanding-ring exact search ----------------
__global__ void __launch_bounds__(128) knn_kernel() {
    const int s = blockIdx.x * 128 + threadIdx.x;
    const int b = s >> 13;
    const float4 qp  = g_spts[s];
    const int    orig = g_sidx[s];
    const float qx = qp.x, qy = qp.y, qz = qp.z;
    const float qn = -2.0f * qp.w;              // ||q||^2
    const int cx = cid1(qx), cy = cid1(qy), cz = cid1(qz);

    const float4* __restrict__ sp = g_spts + b * BQ;
    const int*    __restrict__ si = g_sidx + b * BQ;
    const int*    __restrict__ st = g_start[b];

    float dv[KNN];
    int   iv[KNN];

    for (int r = 1; r <= GR; ++r) {
#pragma unroll
        for (int j = 0; j < KNN; j++) { dv[j] = FLT_MAX; iv[j] = 0; }
        float tcut = -FLT_MAX;

        const int zlo = max(cz - r, 0), zhi = min(cz + r, GR - 1);
        const int ylo = max(cy - r, 0), yhi = min(cy + r, GR - 1);
        const int xlo = max(cx - r, 0), xhi = min(cx + r, GR - 1);

        for (int zz = zlo; zz <= zhi; zz++) {
            for (int yy = ylo; yy <= yhi; yy++) {
                const int rowbase = (zz * GR + yy) * GR;
                const int j0 = st[rowbase + xlo];
                const int j1 = st[rowbase + xhi + 1];
                for (int j = j0; j < j1; j++) {
                    const float4 p = sp[j];
                    const float t = fmaf(qx, p.x, fmaf(qy, p.y, fmaf(qz, p.z, p.w)));
                    if (t > tcut) {                 // d2 < current kth
                        const float d2 = fmaf(-2.0f, t, qn);
                        if (d2 < dv[KNN-1]) {
                            dv[KNN-1] = d2; iv[KNN-1] = si[j];
#pragma unroll
                            for (int m = KNN-1; m > 0; --m) {
                                if (dv[m] < dv[m-1]) {
                                    float td = dv[m]; dv[m] = dv[m-1]; dv[m-1] = td;
                                    int   ti = iv[m]; iv[m] = iv[m-1]; iv[m-1] = ti;
                                }
                            }
                            tcut = 0.5f * (qn - dv[KNN-1]);
                        }
                    }
                }
            }
        }

        // guard: min distance to any unscanned cell region (domain faces are open)
        float g = FLT_MAX;
        if (cx - r > 0)      g = fminf(g, qx - (float)(cx - r) * HCELL);
        if (cx + r < GR - 1) g = fminf(g, (float)(cx + r + 1) * HCELL - qx);
        if (cy - r > 0)      g = fminf(g, qy - (float)(cy - r) * HCELL);
        if (cy + r < GR - 1) g = fminf(g, (float)(cy + r + 1) * HCELL - qy);
        if (cz - r > 0)      g = fminf(g, qz - (float)(cz - r) * HCELL);
        if (cz + r < GR - 1) g = fminf(g, (float)(cz + r + 1) * HCELL - qz);

        if (g == FLT_MAX || dv[KNN-1] < g * g) break;
    }

    const int base = (b * BQ + orig) * KNN;
#pragma unroll
    for (int k = 0; k < KNN; k++) {
        g_dist[base + k] = dv[k];
        g_idx [base + k] = iv[k];
    }
}

// ---------------- 3x3 symmetric eigen -> condition ratio (fp32) ----------------
__device__ __forceinline__ float cond_of_gram(
    float g00, float g01, float g02, float g11, float g12, float g22) {
    const float q  = (g00 + g11 + g22) * (1.0f/3.0f);
    const float p1 = g01*g01 + g02*g02 + g12*g12;
    const float b00 = g00 - q, b11 = g11 - q, b22 = g22 - q;
    const float p2 = b00*b00 + b11*b11 + b22*b22 + 2.0f*p1;
    float l0, l2;
    if (p2 <= 0.0f) {
        l0 = q; l2 = q;
    } else {
        const float p   = sqrtf(p2 * (1.0f/6.0f));
        const float inv = 1.0f / p;
        const float c00 = b00*inv, c01 = g01*inv, c02 = g02*inv;
        const float c11 = b11*inv, c12 = g12*inv, c22 = b22*inv;
        float detB = c00*(c11*c22 - c12*c12)
                   - c01*(c01*c22 - c12*c02)
                   + c02*(c01*c12 - c11*c02);
        float r = 0.5f * detB;
        r = fminf(1.0f, fmaxf(-1.0f, r));
        const float phi = acosf(r) * (1.0f/3.0f);
        l0 = q + 2.0f*p*cosf(phi);
        l2 = q + 2.0f*p*cosf(phi + 2.0943951023931953f);  // min eig
    }
    const float s0 = sqrtf(fmaxf(l0, 0.0f));
    const float s2 = sqrtf(fmaxf(l2, 0.0f));
    return s0 / (s2 + s0);
}

// ---------------- per-query condition numbers + squared diff ----------------
__global__ void __launch_bounds__(128) cond_kernel(
    const float* __restrict__ ref, const float* __restrict__ pts) {
    __shared__ double ssum[128];
    const int tid = threadIdx.x;
    const int q   = blockIdx.x * 128 + tid;
    const int b   = q >> 13;
    const float* rp = ref + (size_t)b * BQ * 3;
    const float* pp = pts + (size_t)b * BQ * 3;

    int   idxs[KNN];
    float msk [KNN];
    float nball = 0.0f;
#pragma unroll
    for (int k = 0; k < KNN; k++) {
        const float d = g_dist[q*KNN + k];
        idxs[k] = g_idx[q*KNN + k];
        const float m = (d < BALL2) ? 1.0f : 0.0f;
        msk[k] = m; nball += m;
    }
    const float invn = 1.0f / nball;

    float px[KNN], py[KNN], pz[KNN];

    // ---- ref branch: masked gather ----
    float cx = 0.f, cy = 0.f, cz = 0.f;
#pragma unroll
    for (int k = 0; k < KNN; k++) {
        const int id = idxs[k];
        float x = rp[3*id+0] * msk[k];
        float y = rp[3*id+1] * msk[k];
        float z = rp[3*id+2] * msk[k];
        px[k] = x; py[k] = y; pz[k] = z;
        cx += x; cy += y; cz += z;
    }
    cx *= invn; cy *= invn; cz *= invn;
    float g00=0.f, g01=0.f, g02=0.f, g11=0.f, g12=0.f, g22=0.f;
#pragma unroll
    for (int k = 0; k < KNN; k++) {
        const float dx = px[k] - cx;
        const float dy = py[k] - cy;
        const float dz = pz[k] - cz;
        g00 += dx*dx; g01 += dx*dy; g02 += dx*dz;
        g11 += dy*dy; g12 += dy*dz; g22 += dz*dz;
    }
    const float cond_ref = cond_of_gram(g00, g01, g02, g11, g12, g22);

    // ---- points branch: UNmasked gather (reference discards the mask here) ----
    cx = 0.f; cy = 0.f; cz = 0.f;
#pragma unroll
    for (int k = 0; k < KNN; k++) {
        const int id = idxs[k];
        float x = pp[3*id+0];
        float y = pp[3*id+1];
        float z = pp[3*id+2];
        px[k] = x; py[k] = y; pz[k] = z;
        cx += x; cy += y; cz += z;
    }
    cx *= invn; cy *= invn; cz *= invn;
    g00=0.f; g01=0.f; g02=0.f; g11=0.f; g12=0.f; g22=0.f;
#pragma unroll
    for (int k = 0; k < KNN; k++) {
        const float dx = px[k] - cx;
        const float dy = py[k] - cy;
        const float dz = pz[k] - cz;
        g00 += dx*dx; g01 += dx*dy; g02 += dx*dz;
        g11 += dy*dy; g12 += dy*dz; g22 += dz*dz;
    }
    const float cond_p = cond_of_gram(g00, g01, g02, g11, g12, g22);

    const double diff = (double)cond_p - (double)cond_ref;
    ssum[tid] = diff * diff;
    __syncthreads();
    for (int st = 64; st > 0; st >>= 1) {
        if (tid < st) ssum[tid] += ssum[tid + st];
        __syncthreads();
    }
    if (tid == 0) g_partial[blockIdx.x] = ssum[0];
}

// ---------------- deterministic final reduction ----------------
__global__ void reduce_kernel(float* __restrict__ out) {
    __shared__ double s[128];
    const int tid = threadIdx.x;
    s[tid] = g_partial[tid];
    __syncthreads();
    for (int st = 64; st > 0; st >>= 1) {
        if (tid < st) s[tid] += s[tid + st];
        __syncthreads();
    }
    if (tid == 0) out[0] = (float)(s[0] / (double)NQ);
}

// ---------------- launch ----------------
extern "C" void kernel_launch(void* const* d_in, const int* in_sizes, int n_in,
                              void* d_out, int out_size) {
    const float* ref = (const float*)d_in[0];
    const float* pts = (const float*)d_in[1];
    zero_kernel<<<(NB*GC + 255)/256, 256>>>();
    count_kernel<<<(NQ + 255)/256, 256>>>(ref);
    scan_kernel<<<NB, GC>>>();
    scatter_kernel<<<(NQ + 255)/256, 256>>>();
    knn_kernel<<<NQ/128, 128>>>();
    cond_kernel<<<NQ/128, 128>>>(ref, pts);
    reduce_kernel<<<1, 128>>>((float*)d_out);
}

// round 3
// speedup vs baseline: 4.8462x; 1.3176x over previous
#include <cuda_runtime.h>
#include <math.h>
#include <float.h>

#define BQ    8192
#define NB    2
#define NQ    (NB*BQ)
#define KNN   16
#define BALL2 0.2f
#define GR    8
#define GC    (GR*GR*GR)
#define HCELL 0.125f
#define NBLK  256            // blocks in knn/cond kernel

// ---------------- scratch (no allocations allowed) ----------------
__device__ float4 g_db[NQ];          // packed points, input order
__device__ int    g_pcell[NQ];       // cell per point
__device__ int    g_start[NB][GC+1]; // per-batch exclusive prefix
__device__ float4 g_spts[NQ];        // cell-sorted points (x,y,z,-0.5*||p||^2)
__device__ int    g_sidx[NQ];        // original local index of sorted point
__device__ double g_partial[NBLK];
__device__ int    g_done;

__device__ __forceinline__ int cid1(float v) {
    int c = (int)(v * (float)GR);
    return min(GR - 1, max(c, 0));
}

// ================= fused grid build: count + scan + scatter =================
// 2 blocks (one per batch), 1024 threads each.
__global__ void __launch_bounds__(1024) build_kernel(const float* __restrict__ ref) {
    __shared__ int scnt[GC];
    __shared__ int sscan[GC];
    __shared__ int scur[GC];
    const int b = blockIdx.x;
    const int t = threadIdx.x;
    if (b == 0 && t == 0) g_done = 0;

    if (t < GC) scnt[t] = 0;
    __syncthreads();

    const float* rp = ref + (size_t)b * BQ * 3;
    // phase A: pack + count
#pragma unroll
    for (int k = 0; k < 8; k++) {
        const int i = k * 1024 + t;
        const float x = rp[3*i+0], y = rp[3*i+1], z = rp[3*i+2];
        const float n = x*x + y*y + z*z;
        g_db[b*BQ + i] = make_float4(x, y, z, -0.5f*n);
        const int cell = (cid1(z) * GR + cid1(y)) * GR + cid1(x);
        g_pcell[b*BQ + i] = cell;
        atomicAdd(&scnt[cell], 1);
    }
    __syncthreads();

    // phase B: inclusive scan of 512 counts (Hillis-Steele, uniform barriers)
    if (t < GC) sscan[t] = scnt[t];
    __syncthreads();
    for (int off = 1; off < GC; off <<= 1) {
        int v = 0;
        if (t < GC && t >= off) v = sscan[t - off];
        __syncthreads();
        if (t < GC) sscan[t] += v;
        __syncthreads();
    }
    if (t < GC) {
        g_start[b][t + 1] = sscan[t];
        scur[t] = sscan[t] - scnt[t];
    }
    if (t == 0) g_start[b][0] = 0;
    __syncthreads();

    // phase C: scatter into sorted order
#pragma unroll
    for (int k = 0; k < 8; k++) {
        const int i = k * 1024 + t;
        const int cell = g_pcell[b*BQ + i];
        const int pos = atomicAdd(&scur[cell], 1);
        g_spts[b*BQ + pos] = g_db[b*BQ + i];
        g_sidx[b*BQ + pos] = i;
    }
}

// ---------------- 3x3 symmetric eigen -> condition ratio (fp32) ----------------
__device__ __forceinline__ float cond_of_gram(
    float g00, float g01, float g02, float g11, float g12, float g22) {
    const float q  = (g00 + g11 + g22) * (1.0f/3.0f);
    const float p1 = g01*g01 + g02*g02 + g12*g12;
    const float b00 = g00 - q, b11 = g11 - q, b22 = g22 - q;
    const float p2 = b00*b00 + b11*b11 + b22*b22 + 2.0f*p1;
    float l0, l2;
    if (p2 <= 0.0f) {
        l0 = q; l2 = q;
    } else {
        const float p   = sqrtf(p2 * (1.0f/6.0f));
        const float inv = 1.0f / p;
        const float c00 = b00*inv, c01 = g01*inv, c02 = g02*inv;
        const float c11 = b11*inv, c12 = g12*inv, c22 = b22*inv;
        float detB = c00*(c11*c22 - c12*c12)
                   - c01*(c01*c22 - c12*c02)
                   + c02*(c01*c12 - c11*c02);
        float r = 0.5f * detB;
        r = fminf(1.0f, fmaxf(-1.0f, r));
        const float phi = acosf(r) * (1.0f/3.0f);
        l0 = q + 2.0f*p*cosf(phi);
        l2 = q + 2.0f*p*cosf(phi + 2.0943951023931953f);  // min eig
    }
    const float s0 = sqrtf(fmaxf(l0, 0.0f));
    const float s2 = sqrtf(fmaxf(l2, 0.0f));
    return s0 / (s2 + s0);
}

// ================= fused knn + cond + reduction =================
// 256 blocks x 256 threads. 4 lanes per query -> 64 queries per block.
__global__ void __launch_bounds__(256) knncond_kernel(
    const float* __restrict__ ref, const float* __restrict__ pts,
    float* __restrict__ out) {
    __shared__ float  sdist[64 * KNN];
    __shared__ int    sind [64 * KNN];
    __shared__ double ssum [64];
    __shared__ double sred [NBLK];
    __shared__ int    sdone;

    const int tid = threadIdx.x;
    const int lg  = tid & 3;
    const int qs  = tid >> 2;                 // query slot 0..63
    const int blk = blockIdx.x;
    const int b   = blk >> 7;                 // 128 blocks per batch
    const int s   = b * BQ + (blk & 127) * 64 + qs;   // sorted query index

    const float4 qp = g_spts[s];
    const float qx = qp.x, qy = qp.y, qz = qp.z;
    const float qn = -2.0f * qp.w;            // ||q||^2
    const int cx = cid1(qx), cy = cid1(qy), cz = cid1(qz);

    const float4* __restrict__ sp = g_spts + b * BQ;
    const int*    __restrict__ si = g_sidx + b * BQ;
    const int*    __restrict__ st = g_start[b];

    float dv[KNN];
    int   iv[KNN];

    for (int r = 1; r <= GR; ++r) {
#pragma unroll
        for (int j = 0; j < KNN; j++) { dv[j] = FLT_MAX; iv[j] = 0x7fffffff; }
        float tcut = -FLT_MAX;

        const int zlo = max(cz - r, 0), zhi = min(cz + r, GR - 1);
        const int ylo = max(cy - r, 0), yhi = min(cy + r, GR - 1);
        const int xlo = max(cx - r, 0), xhi = min(cx + r, GR - 1);

        for (int zz = zlo; zz <= zhi; zz++) {
            for (int yy = ylo; yy <= yhi; yy++) {
                const int rowbase = (zz * GR + yy) * GR;
                const int j0 = st[rowbase + xlo];
                const int j1 = st[rowbase + xhi + 1];
                for (int j = j0 + lg; j < j1; j += 4) {   // lane-strided scan
                    const float4 p = sp[j];
                    const float t = fmaf(qx, p.x, fmaf(qy, p.y, fmaf(qz, p.z, p.w)));
                    if (t > tcut) {                        // d2 < lane kth
                        const float d2 = fmaf(-2.0f, t, qn);
                        if (d2 < dv[KNN-1]) {
                            dv[KNN-1] = d2; iv[KNN-1] = si[j];
#pragma unroll
                            for (int m = KNN-1; m > 0; --m) {
                                if (dv[m] < dv[m-1]) {
                                    float td = dv[m]; dv[m] = dv[m-1]; dv[m-1] = td;
                                    int   ti = iv[m]; iv[m] = iv[m-1]; iv[m-1] = ti;
                                }
                            }
                            tcut = 0.5f * (qn - dv[KNN-1]);
                        }
                    }
                }
            }
        }

        // merge the 4 sorted lane lists -> exact union top-16 into shared
        float kth = FLT_MAX;
        for (int m = 0; m < KNN; m++) {
            float bd = dv[0]; int bi = iv[0];
#pragma unroll
            for (int off = 1; off < 4; off <<= 1) {
                const float od = __shfl_xor_sync(0xffffffffu, bd, off, 4);
                const int   oi = __shfl_xor_sync(0xffffffffu, bi, off, 4);
                if (od < bd || (od == bd && oi < bi)) { bd = od; bi = oi; }
            }
            if (dv[0] == bd && iv[0] == bi) {              // owning lane pops
#pragma unroll
                for (int j = 0; j < KNN-1; j++) { dv[j] = dv[j+1]; iv[j] = iv[j+1]; }
                dv[KNN-1] = FLT_MAX; iv[KNN-1] = 0x7fffffff;
            }
            if (lg == 0) { sdist[qs*KNN + m] = bd; sind[qs*KNN + m] = bi; }
            kth = bd;
        }

        // exact guard: min distance from q to any unscanned region
        float g = FLT_MAX;
        if (cx - r > 0)      g = fminf(g, qx - (float)(cx - r) * HCELL);
        if (cx + r < GR - 1) g = fminf(g, (float)(cx + r + 1) * HCELL - qx);
        if (cy - r > 0)      g = fminf(g, qy - (float)(cy - r) * HCELL);
        if (cy + r < GR - 1) g = fminf(g, (float)(cy + r + 1) * HCELL - qy);
        if (cz - r > 0)      g = fminf(g, qz - (float)(cz - r) * HCELL);
        if (cz + r < GR - 1) g = fminf(g, (float)(cz + r + 1) * HCELL - qz);

        if (g == FLT_MAX || kth < g * g) break;
    }
    __syncthreads();

    // ---- cond phase: one thread per query slot ----
    if (tid < 64) {
        const float* rp = ref + (size_t)b * BQ * 3;
        const float* pp = pts + (size_t)b * BQ * 3;

        int   idxs[KNN];
        float msk [KNN];
        float nball = 0.0f;
#pragma unroll
        for (int k = 0; k < KNN; k++) {
            const float d = sdist[tid*KNN + k];
            idxs[k] = sind[tid*KNN + k];
            const float m = (d < BALL2) ? 1.0f : 0.0f;
            msk[k] = m; nball += m;
        }
        const float invn = 1.0f / nball;

        float px[KNN], py[KNN], pz[KNN];

        // ref branch: masked gather
        float cxm = 0.f, cym = 0.f, czm = 0.f;
#pragma unroll
        for (int k = 0; k < KNN; k++) {
            const int id = idxs[k];
            const float x = rp[3*id+0] * msk[k];
            const float y = rp[3*id+1] * msk[k];
            const float z = rp[3*id+2] * msk[k];
            px[k] = x; py[k] = y; pz[k] = z;
            cxm += x; cym += y; czm += z;
        }
        cxm *= invn; cym *= invn; czm *= invn;
        float g00=0.f,g01=0.f,g02=0.f,g11=0.f,g12=0.f,g22=0.f;
#pragma unroll
        for (int k = 0; k < KNN; k++) {
            const float dx = px[k]-cxm, dy = py[k]-cym, dz = pz[k]-czm;
            g00 += dx*dx; g01 += dx*dy; g02 += dx*dz;
            g11 += dy*dy; g12 += dy*dz; g22 += dz*dz;
        }
        const float cond_ref = cond_of_gram(g00,g01,g02,g11,g12,g22);

        // points branch: UNmasked gather (reference discards the mask here)
        cxm = 0.f; cym = 0.f; czm = 0.f;
#pragma unroll
        for (int k = 0; k < KNN; k++) {
            const int id = idxs[k];
            const float x = pp[3*id+0];
            const float y = pp[3*id+1];
            const float z = pp[3*id+2];
            px[k] = x; py[k] = y; pz[k] = z;
            cxm += x; cym += y; czm += z;
        }
        cxm *= invn; cym *= invn; czm *= invn;
        g00=0.f;g01=0.f;g02=0.f;g11=0.f;g12=0.f;g22=0.f;
#pragma unroll
        for (int k = 0; k < KNN; k++) {
            const float dx = px[k]-cxm, dy = py[k]-cym, dz = pz[k]-czm;
            g00 += dx*dx; g01 += dx*dy; g02 += dx*dz;
            g11 += dy*dy; g12 += dy*dz; g22 += dz*dz;
        }
        const float cond_p = cond_of_gram(g00,g01,g02,g11,g12,g22);

        const double diff = (double)cond_p - (double)cond_ref;
        ssum[tid] = diff * diff;
    }
    __syncthreads();

    // block tree-reduce 64 doubles (deterministic)
    for (int stp = 32; stp > 0; stp >>= 1) {
        if (tid < stp) ssum[tid] += ssum[tid + stp];
        __syncthreads();
    }
    if (tid == 0) g_partial[blk] = ssum[0];

    // completion-counter final reduction (deterministic fixed-order sum)
    if (tid == 0) {
        __threadfence();
        const int v = atomicAdd(&g_done, 1);
        sdone = (v == NBLK - 1);
    }
    __syncthreads();
    if (sdone) {
        __threadfence();
        sred[tid] = g_partial[tid];
        __syncthreads();
        for (int stp = 128; stp > 0; stp >>= 1) {
            if (tid < stp) sred[tid] += sred[tid + stp];
            __syncthreads();
        }
        if (tid == 0) out[0] = (float)(sred[0] / (double)NQ);
    }
}

// ---------------- launch ----------------
extern "C" void kernel_launch(void* const* d_in, const int* in_sizes, int n_in,
                              void* d_out, int out_size) {
    const float* ref = (const float*)d_in[0];
    const float* pts = (const float*)d_in[1];
    build_kernel<<<NB, 1024>>>(ref);
    knncond_kernel<<<NBLK, 256>>>(ref, pts, (float*)d_out);
}